// round 14
// baseline (speedup 1.0000x reference)
#include <cuda_runtime.h>
#include <cuda_fp16.h>
#include <math.h>

// B=4, C=2, H=W=1024, DS=4 -> 256x256, NUM_SEEDS=32, 15 steps, pool 7x7.
// Register flood v2: 16 warps, warp(wr,wc) = rows 26wr..+25 x cols 26wc..+25.
// Lane = row (halo lanes 0-2 / 29-31); 17 half2 regs/lane (4 col-halo regs).
#define NCH   128
#define RST   53                       // uints per row in Gv (odd mod 32 -> conflict-free)
#define GVSZ  (104 * RST * 4)          // 22048
#define GGOFF (2 * GVSZ)               // 44096
#define GGSZ  (104 * 16)               // 1664
#define MSOFF (GGOFF + 2 * GGSZ)       // 47424
#define SMEM_BYTES (MSOFF + 97 * 208)  // 67600

__device__ __half   g_road[4 * 256 * 256];
__device__ unsigned g_gtb[4 * 256 * 8];
__device__ int   g_sr[NCH];
__device__ int   g_sc[NCH];
__device__ int   g_scnt[NCH];
__device__ float g_sv[NCH];
__device__ float g_partial[NCH];
__device__ int   g_done;

__global__ void k_prep(const float* __restrict__ cls, const int* __restrict__ lab,
                       const float4* __restrict__ seeds) {
    if (blockIdx.x < 1024) {
        int idx = blockIdx.x * 256 + threadIdx.x;
        int j = idx & 255, i = (idx >> 8) & 255, b = idx >> 16;
        const float* c0 = cls + (size_t)(b * 2 + 0) * 1048576;
        const float* c1 = cls + (size_t)(b * 2 + 1) * 1048576;
        int r1 = 4 * i + 1, r2 = 4 * i + 2, cc = 4 * j;
        float4 a0 = *(const float4*)(c0 + r1 * 1024 + cc);
        float4 a1 = *(const float4*)(c1 + r1 * 1024 + cc);
        float4 b0 = *(const float4*)(c0 + r2 * 1024 + cc);
        float4 b1 = *(const float4*)(c1 + r2 * 1024 + cc);
        float p1 = 1.f / (1.f + expf(a0.y - a1.y));
        float p2 = 1.f / (1.f + expf(a0.z - a1.z));
        float p3 = 1.f / (1.f + expf(b0.y - b1.y));
        float p4 = 1.f / (1.f + expf(b0.z - b1.z));
        g_road[idx] = __float2half(0.25f * (p1 + p2 + p3 + p4));
        int g = lab[((size_t)b * 1024 + 4 * i) * 1024 + 4 * j];
        unsigned bits = __ballot_sync(0xffffffffu, g != 0);
        if ((threadIdx.x & 31) == 0)
            g_gtb[((size_t)b * 256 + i) * 8 + (j >> 5)] = bits;
    }
    {
        const unsigned n4 = (4 * 32 * 256 * 256) / 4;
        for (unsigned i = blockIdx.x * 256u + threadIdx.x; i < n4; i += 2048u * 256u) {
            float4 v = seeds[i];
            if (v.x > 0.f || v.y > 0.f || v.z > 0.f || v.w > 0.f) {
                float vals[4] = {v.x, v.y, v.z, v.w};
                #pragma unroll
                for (int k = 0; k < 4; k++) if (vals[k] > 0.f) {
                    unsigned idx = i * 4u + k;
                    int ch = idx >> 16;
                    g_sr[ch] = (idx >> 8) & 255;
                    g_sc[ch] = idx & 255;
                    g_sv[ch] = vals[k];
                    g_scnt[ch] = 1;
                }
            }
        }
    }
    asm volatile("griddepcontrol.launch_dependents;" ::: "memory");
}

__device__ __forceinline__ unsigned getword(const unsigned* row, int start) {
    int w = start >> 5;
    int sh = start & 31;
    unsigned lo = ((unsigned)w < 8u) ? row[w] : 0u;
    unsigned hi = ((unsigned)(w + 1) < 8u) ? row[w + 1] : 0u;
    return __funnelshift_r(lo, hi, sh);
}
__device__ __forceinline__ uint4 bshl(uint4 v, int s) {
    return make_uint4(v.x << s, __funnelshift_l(v.x, v.y, s),
                      __funnelshift_l(v.y, v.z, s), __funnelshift_l(v.z, v.w, s));
}
__device__ __forceinline__ uint4 bshr(uint4 v, int s) {
    return make_uint4(__funnelshift_r(v.x, v.y, s), __funnelshift_r(v.y, v.z, s),
                      __funnelshift_r(v.z, v.w, s), v.w >> s);
}
__device__ __forceinline__ uint4 bor(uint4 a, uint4 b) {
    return make_uint4(a.x | b.x, a.y | b.y, a.z | b.z, a.w | b.w);
}
__device__ __forceinline__ unsigned hmax2u(unsigned a, unsigned b) {
    __half2 r = __hmax2(*(__half2*)&a, *(__half2*)&b);
    return *(unsigned*)&r;
}
__device__ __forceinline__ unsigned hmin2u(unsigned a, unsigned b) {
    __half2 r = __hmin2(*(__half2*)&a, *(__half2*)&b);
    return *(unsigned*)&r;
}
#define FSR(a, b) __funnelshift_r((a), (b), 16)

__global__ void __launch_bounds__(512, 1) k_flood(float* __restrict__ out) {
    extern __shared__ char sm[];
    __shared__ float wpart[16];
    __shared__ int   s_last;

    unsigned tid = threadIdx.x;
    int w = tid >> 5, l = tid & 31;
    int wr = w >> 2, wc = w & 3;
    int rr = 26 * wr + l - 3;           // lane's row (-3..106)
    bool own  = (l >= 3 && l <= 28);
    bool halo = (l <= 2 && wr > 0) || (l >= 29 && wr < 3);
    int cbase = 26 * wc;
    int gk0   = 13 * wc;
    int ch = blockIdx.x, b = ch >> 5;
    const float c0log = -logf(1.0f - 1e-7f);

    // pre-dependency: zero all exchange buffers + mask staging
    {
        uint4 z = make_uint4(0, 0, 0, 0);
        uint4* p = (uint4*)sm;
        for (int i = tid; i < SMEM_BYTES / 16; i += 512) p[i] = z;
    }
    asm volatile("griddepcontrol.wait;" ::: "memory");
    __syncthreads();

    bool hasseed = (g_scnt[ch] != 0);
    if (hasseed) {
        int sr = g_sr[ch], sc = g_sc[ch];
        float sv = g_sv[ch];
        int gr0 = sr - 48, gc0 = sc - 48;

        // ---- fill mask staging (97 rows x 104 halfs, pitch 208B) ----
        for (unsigned idx = tid; idx < 97u * 97u; idx += 512) {
            unsigned y = idx / 97u;
            unsigned x = idx - y * 97u;
            int gy = gr0 + (int)y, gx = gc0 + (int)x;
            __half mv = __ushort_as_half((unsigned short)0);
            if ((unsigned)gy < 256u && (unsigned)gx < 256u)
                mv = g_road[(b << 16) + (gy << 8) + gx];
            *(__half*)(sm + MSOFF + y * 208 + 2 * x) = mv;
        }
        __syncthreads();

        // ---- per-lane registers ----
        unsigned v[17], m[13];
        #pragma unroll
        for (int k = 0; k < 17; k++) v[k] = 0u;
        #pragma unroll
        for (int k = 0; k < 13; k++) m[k] = 0u;
        if (rr >= 0 && rr <= 96) {
            const char* srcm = sm + MSOFF + rr * 208 + 2 * cbase;
            #pragma unroll
            for (int k = 0; k < 13; k++) m[k] = *(const unsigned*)(srcm + 4 * k);
        }
        uint4 grow = make_uint4(0, 0, 0, 0), gmask = make_uint4(0, 0, 0, 0);
        if (rr >= 0 && rr <= 96) {
            int gy = gr0 + rr;
            if ((unsigned)gy < 256u) {
                const unsigned* row = &g_gtb[((size_t)b * 256 + gy) * 8];
                gmask.x = getword(row, gc0);
                gmask.y = getword(row, gc0 + 32);
                gmask.z = getword(row, gc0 + 64);
                gmask.w = getword(row, gc0 + 96) & 1u;
            }
        }
        unsigned seedlo = (unsigned)__half_as_ushort(__float2half(sv));
        if (wr == 1 && wc == 1 && l == 25) v[13] = seedlo;   // row48 col48 (reg13 lo)
        if (wr == 1 && l == 25) grow.y |= (1u << 16);

        #pragma unroll 1
        for (int it = 0; it < 15; it++) {
            int R = 3 * (it + 1);
            bool wact = (26 * wr <= 48 + R) && (26 * wr + 25 >= 48 - R) &&
                        (cbase <= 48 + R) && (cbase + 25 >= 48 - R);
            char* gv = sm + (it & 1) * GVSZ;
            char* gg = sm + GGOFF + (it & 1) * GGSZ;

            // ---- stage 1: publish current state ----
            if (own) {
                if (wact) {
                    unsigned* dst = (unsigned*)gv + rr * RST + gk0;
                    #pragma unroll
                    for (int k = 0; k < 13; k++) dst[k] = v[k + 2];
                }
                if (wc == 0) *(uint4*)(gg + rr * 16) = grow;
            }
            __syncthreads();
            // ---- stage 2: refresh halos ----
            if (wact) {
                const unsigned* basep = (const unsigned*)gv + (rr < 0 ? 0 : rr) * RST;
                if (own) {
                    if (wc > 0) { v[0] = basep[gk0 - 2]; v[1] = basep[gk0 - 1]; }
                    if (wc < 3) { v[15] = basep[gk0 + 13]; v[16] = basep[gk0 + 14]; }
                } else if (halo) {
                    #pragma unroll
                    for (int k = 0; k < 17; k++) {
                        int gk = gk0 - 2 + k;
                        v[k] = (gk >= 0 && gk < 52) ? basep[gk] : 0u;
                    }
                }
            }
            if (halo) grow = *(const uint4*)(gg + rr * 16);

            // ---- float update (warp-uniform gate; shuffles full-mask safe) ----
            if (wact) {
                unsigned a[16], bb[15], h[13];
                #pragma unroll
                for (int k = 0; k < 16; k++)
                    a[k] = hmax2u(v[k], FSR(v[k], v[k + 1]));
                #pragma unroll
                for (int k = 0; k < 15; k++)
                    bb[k] = hmax2u(a[k], a[k + 1]);
                #pragma unroll
                for (int k = 0; k < 13; k++)
                    h[k] = hmax2u(FSR(bb[k], bb[k + 1]), bb[k + 2]);
                #pragma unroll
                for (int k = 0; k < 13; k++) {
                    unsigned p  = hmax2u(h[k], __shfl_down_sync(0xffffffffu, h[k], 1));
                    unsigned b4 = hmax2u(p,   __shfl_down_sync(0xffffffffu, p, 2));
                    unsigned o  = hmax2u(b4,  __shfl_up_sync(0xffffffffu, b4, 3));
                    v[k + 2] = hmin2u(o, m[k]);
                }
                if (wr == 1 && wc == 1 && l == 25) v[13] = hmax2u(v[13], seedlo);
            }
            // ---- gt bitwise flood (always; redundant per wc, validated R13) ----
            {
                uint4 gh = bor(grow, bor(bshl(grow, 1), bshr(grow, 1)));
                gh = bor(gh, bor(bshl(grow, 2), bshr(grow, 2)));
                gh = bor(gh, bor(bshl(grow, 3), bshr(grow, 3)));
                uint4 p, b4, o;
                p.x = gh.x | __shfl_down_sync(0xffffffffu, gh.x, 1);
                p.y = gh.y | __shfl_down_sync(0xffffffffu, gh.y, 1);
                p.z = gh.z | __shfl_down_sync(0xffffffffu, gh.z, 1);
                p.w = gh.w | __shfl_down_sync(0xffffffffu, gh.w, 1);
                b4.x = p.x | __shfl_down_sync(0xffffffffu, p.x, 2);
                b4.y = p.y | __shfl_down_sync(0xffffffffu, p.y, 2);
                b4.z = p.z | __shfl_down_sync(0xffffffffu, p.z, 2);
                b4.w = p.w | __shfl_down_sync(0xffffffffu, p.w, 2);
                o.x = b4.x | __shfl_up_sync(0xffffffffu, b4.x, 3);
                o.y = b4.y | __shfl_up_sync(0xffffffffu, b4.y, 3);
                o.z = b4.z | __shfl_up_sync(0xffffffffu, b4.z, 3);
                o.w = b4.w | __shfl_up_sync(0xffffffffu, b4.w, 3);
                grow.x = o.x & gmask.x;
                grow.y = o.y & gmask.y;
                grow.z = o.z & gmask.z;
                grow.w = o.w & gmask.w;
                if (wr == 1 && l == 25) grow.y |= (1u << 16);
            }
        }

        // ---- BCE from registers (owned lanes/cols only; unique coverage) ----
        int ylo = 3 > -gr0 ? 3 : -gr0;
        int yhi = 93 < 255 - gr0 ? 93 : 255 - gr0;
        int xlo = 3 > -gc0 ? 3 : -gc0;
        int xhi = 93 < 255 - gc0 ? 93 : 255 - gc0;
        float pm = 1.0f;
        int   pe = 0;
        if (own && rr >= ylo && rr <= yhi) {
            #pragma unroll
            for (int k = 0; k < 13; k++) {
                int c0 = cbase + 2 * k, c1 = c0 + 1;
                if (c1 < xlo || c0 > xhi) continue;
                float2 f = __half22float2(*(__half2*)&v[k + 2]);
                int w0i = c0 >> 5, w1i = c1 >> 5;
                unsigned word0 = w0i == 0 ? grow.x : w0i == 1 ? grow.y : w0i == 2 ? grow.z : grow.w;
                unsigned word1 = w1i == 0 ? grow.x : w1i == 1 ? grow.y : w1i == 2 ? grow.z : grow.w;
                if (c0 >= xlo && c0 <= xhi) {
                    float p = fminf(fmaxf(f.x, 1e-7f), 1.0f - 1e-7f);
                    pm *= ((word0 >> (c0 & 31)) & 1u) ? p : (1.0f - p);
                }
                if (c1 >= xlo && c1 <= xhi) {
                    float p = fminf(fmaxf(f.y, 1e-7f), 1.0f - 1e-7f);
                    pm *= ((word1 >> (c1 & 31)) & 1u) ? p : (1.0f - p);
                }
                int bi = __float_as_int(pm);
                pe += (bi >> 23) - 127;
                pm = __int_as_float((bi & 0x007fffff) | 0x3f800000);
            }
        }
        float local = -(__logf(pm) + (float)pe * 0.69314718056f);
        #pragma unroll
        for (int off = 16; off; off >>= 1)
            local += __shfl_down_sync(0xffffffffu, local, off);
        if (l == 0) wpart[w] = local;
        __syncthreads();
        if (tid == 0) {
            float s = 0.f;
            #pragma unroll
            for (int k = 0; k < 16; k++) s += wpart[k];
            float area = (float)((yhi - ylo + 1) * (xhi - xlo + 1));
            s += (65536.0f - area) * c0log;
            g_partial[ch] = s;
        }
    } else {
        if (tid == 0) g_partial[ch] = 65536.0f * c0log;
    }

    // ---- last-block finalize ----
    if (tid == 0) {
        __threadfence();
        int old = atomicAdd(&g_done, 1);
        s_last = (old == NCH - 1);
    }
    __syncthreads();
    if (s_last && tid < 32) {
        float fv = g_partial[tid] + g_partial[tid + 32] +
                   g_partial[tid + 64] + g_partial[tid + 96];
        #pragma unroll
        for (int off = 16; off; off >>= 1)
            fv += __shfl_down_sync(0xffffffffu, fv, off);
        if (tid == 0) {
            out[0] = 0.5f * fv / 8388608.0f;
            g_done = 0;
        }
    }
}

extern "C" void kernel_launch(void* const* d_in, const int* in_sizes, int n_in,
                              void* d_out, int out_size) {
    const float* cls = (const float*)d_in[0];
    const int* lab   = (const int*)d_in[1];
    const float4* seeds = (const float4*)d_in[2];

    cudaFuncSetAttribute(k_flood, cudaFuncAttributeMaxDynamicSharedMemorySize, SMEM_BYTES);

    k_prep<<<2048, 256>>>(cls, lab, seeds);

    cudaLaunchConfig_t cfg = {};
    cfg.gridDim = dim3(128, 1, 1);
    cfg.blockDim = dim3(512, 1, 1);
    cfg.dynamicSmemBytes = SMEM_BYTES;
    cfg.stream = 0;
    cudaLaunchAttribute attr[1];
    attr[0].id = cudaLaunchAttributeProgrammaticStreamSerialization;
    attr[0].val.programmaticStreamSerializationAllowed = 1;
    cfg.attrs = attr;
    cfg.numAttrs = 1;
    float* outp = (float*)d_out;
    cudaError_t e = cudaLaunchKernelEx(&cfg, k_flood, outp);
    if (e != cudaSuccess) {
        k_flood<<<128, 512, SMEM_BYTES>>>(outp);
    }
}